// round 1
// baseline (speedup 1.0000x reference)
#include <cuda_runtime.h>
#include <cuda_bf16.h>
#include <math.h>

// Problem constants
#define BATCH 8
#define CIN   32
#define CMID  16
#define COUT  32
#define HH    384
#define WW    384
#define PLANE (HH*WW)            // 147456
#define NPLANES (BATCH*CIN)      // 256
#define NTAPS 25

// ---- scratch (device globals; no allocation allowed) ----
__device__ float g_stats[NPLANES * 13];          // per (b,ci): T, R0..R2, R381..R383, C0..C2, C381..C383
__device__ float g_W25[CIN * NTAPS * CMID];      // folded stage-1 conv weights [ci][tap][c]
__device__ float g_M[BATCH * COUT * CMID];       // per-batch pointwise weights
__device__ float g_beta[BATCH * COUT];           // per-batch bias

// ============================================================
// Kernel A: per-plane stats. grid = 256 blocks (one per b,ci), 256 threads.
// ============================================================
__global__ void stats_kernel(const float* __restrict__ x) {
    int plane = blockIdx.x;
    const float* xp = x + (size_t)plane * PLANE;
    int tid = threadIdx.x;

    __shared__ float srow[6];
    __shared__ float red[256];
    if (tid < 6) srow[tid] = 0.f;
    __syncthreads();

    float T = 0.f, csum = 0.f;
    // thread covers cols w=tid (always) and w=tid+256 (if tid<128)
    for (int h = 0; h < HH; ++h) {
        float v1 = xp[h * WW + tid];
        T += v1;
        if (tid < 3) csum += v1;                 // cols 0..2
        if (h < 3)        atomicAdd(&srow[h], v1);
        else if (h > 380) atomicAdd(&srow[h - 378], v1);
        if (tid < 128) {
            float v2 = xp[h * WW + tid + 256];
            T += v2;
            if (tid >= 125) csum += v2;          // cols 381..383
            if (h < 3)        atomicAdd(&srow[h], v2);
            else if (h > 380) atomicAdd(&srow[h - 378], v2);
        }
    }
    red[tid] = T;
    __syncthreads();
    for (int s = 128; s > 0; s >>= 1) {
        if (tid < s) red[tid] += red[tid + s];
        __syncthreads();
    }

    float* st = g_stats + plane * 13;
    if (tid == 0) st[0] = red[0];
    if (tid < 6) st[1 + tid] = srow[tid];        // [1..3]=rows 0..2, [4..6]=rows 381..383
    if (tid < 3) st[7 + tid] = csum;             // cols 0..2
    if (tid >= 125 && tid < 128) st[10 + (tid - 125)] = csum;  // cols 381..383
}

// partial sum of x over the valid shifted region for offset (dy,dx), with exact border correction
__device__ __forceinline__ float ps_fun(const float* __restrict__ xp,
                                        const float* __restrict__ st,
                                        int dy, int dx) {
    float s = st[0];
    if (dy > 0)      { for (int r = 0; r <  dy; ++r) s -= st[1 + r]; }
    else if (dy < 0) { for (int r = 0; r < -dy; ++r) s -= st[6 - r]; }
    if (dx > 0)      { for (int c = 0; c <  dx; ++c) s -= st[7 + c]; }
    else if (dx < 0) { for (int c = 0; c < -dx; ++c) s -= st[12 - c]; }
    if (dy != 0 && dx != 0) {
        int r0 = (dy > 0) ? 0 : HH + dy;
        int r1 = (dy > 0) ? dy - 1 : HH - 1;
        int c0 = (dx > 0) ? 0 : WW + dx;
        int c1 = (dx > 0) ? dx - 1 : WW - 1;
        for (int r = r0; r <= r1; ++r)
            for (int c = c0; c <= c1; ++c)
                s += xp[r * WW + c];  // add back doubly-subtracted corner
    }
    return s;
}

// ============================================================
// Kernel B: fold everything into W25 / M / beta. 1 block, 256 threads.
// ============================================================
__global__ void prep_kernel(const float* __restrict__ x,
                            const float* __restrict__ w1, const float* __restrict__ b1,
                            const float* __restrict__ w2, const float* __restrict__ b2,
                            const float* __restrict__ w3, const float* __restrict__ b3,
                            const float* __restrict__ w4, const float* __restrict__ b4,
                            const float* __restrict__ w5, const float* __restrict__ b5,
                            const float* __restrict__ gcn_w, const float* __restrict__ gcn_b,
                            const float* __restrict__ attn,
                            const float* __restrict__ fusion_w, const float* __restrict__ fusion_b) {
    __shared__ float nf[BATCH][5][CMID];   // branch node-feats WITHOUT biases
    __shared__ float zsh[BATCH][CMID];
    __shared__ float fnsh[BATCH][CMID];
    __shared__ float swsh[5];
    int tid = threadIdx.x;

    for (int i = tid; i < BATCH * 5 * CMID; i += 256) ((float*)nf)[i] = 0.f;
    if (tid == 0) {
        float m = attn[0];
        for (int i = 1; i < 5; ++i) m = fmaxf(m, attn[i]);
        float e[5], s = 0.f;
        for (int i = 0; i < 5; ++i) { e[i] = expf(attn[i] - m); s += e[i]; }
        for (int i = 0; i < 5; ++i) swsh[i] = e[i] / s;
    }
    __syncthreads();

    // ---- phase 1: exact per-branch node features (means with zero-padding) ----
    {
        int b = tid >> 5, ci = tid & 31;
        const float* xp = x + (size_t)(b * CIN + ci) * PLANE;
        const float* st = g_stats + (b * CIN + ci) * 13;
        const float invHW = 1.0f / (float)PLANE;
        float xm = st[0] * invHW;
        for (int c = 0; c < CMID; ++c) {
            atomicAdd(&nf[b][0][c], w1[c * CIN + ci] * xm);   // f1: 1x1
            atomicAdd(&nf[b][4][c], w5[c * CIN + ci] * xm);   // f5: 1x1 on GAP
        }
        for (int d = 1; d <= 3; ++d) {
            float ps[9];
            for (int ky = 0; ky < 3; ++ky)
                for (int kx = 0; kx < 3; ++kx)
                    ps[ky * 3 + kx] = ps_fun(xp, st, d * (ky - 1), d * (kx - 1)) * invHW;
            const float* wd = (d == 1) ? w2 : (d == 2) ? w3 : w4;
            for (int c = 0; c < CMID; ++c) {
                float p = 0.f;
                for (int j = 0; j < 9; ++j) p += wd[(c * CIN + ci) * 9 + j] * ps[j];
                atomicAdd(&nf[b][d][c], p);
            }
        }
    }
    __syncthreads();

    // ---- phase 2: z = mean over branches (A_hat uniform) incl. biases ----
    if (tid < BATCH * CMID) {
        int b = tid >> 4, c = tid & 15;
        float s = nf[b][0][c] + nf[b][1][c] + nf[b][2][c] + nf[b][3][c] + nf[b][4][c]
                + b1[c] + b2[c] + b3[c] + b4[c] + b5[c];
        zsh[b][c] = 0.2f * s;
    }
    __syncthreads();

    // ---- phase 3: fn = z @ gcn_w + gcn_b ----
    if (tid < BATCH * CMID) {
        int b = tid >> 4, c = tid & 15;
        float s = gcn_b[c];
        for (int k = 0; k < CMID; ++k) s += zsh[b][k] * gcn_w[k * CMID + c];
        fnsh[b][c] = s;
    }
    __syncthreads();

    // ---- phase 4: M, beta ----
    {
        int b = tid >> 5, co = tid & 31;
        float bt = fusion_b[co];
        for (int c = 0; c < CMID; ++c) {
            float K = swsh[0] * b1[c] + swsh[1] * b2[c] + swsh[2] * b3[c] + swsh[3] * b4[c]
                    + swsh[4] * (nf[b][4][c] + b5[c]);       // f5 value (constant map)
            float m = fusion_w[co * CMID + c] * fnsh[b][c];
            g_M[(b * COUT + co) * CMID + c] = m;
            bt += m * K;
        }
        g_beta[b * COUT + co] = bt;
    }

    // ---- phase 5: folded 25-tap stage-1 weights, scaled by softmax weights ----
    // tap order: t<9:  dy=-3,-2,-1 groups of 3 (dx=(k-1)*|dy|)
    //            t in 9..15: dy=0, dx=t-12
    //            t>=16: dy=+1,+2,+3 groups of 3
    for (int idx = tid; idx < CIN * NTAPS * CMID; idx += 256) {
        int ci = idx / (NTAPS * CMID);
        int r = idx - ci * (NTAPS * CMID);
        int t = r >> 4;
        int c = r & 15;
        int dyo, dx;
        if (t < 9)       { int g = t / 3; dyo = g - 3; dx = (t - g * 3 - 1) * (3 - g); }
        else if (t < 16) { dyo = 0; dx = t - 12; }
        else             { int g = (t - 16) / 3; dyo = g + 1; dx = ((t - 16) - g * 3 - 1) * (g + 1); }
        float v = 0.f;
        if (dyo == 0 && dx == 0) v += swsh[0] * w1[c * CIN + ci];
        for (int d = 1; d <= 3; ++d) {
            const float* wd = (d == 1) ? w2 : (d == 2) ? w3 : w4;
            bool iny = (dyo == 0 || dyo == d || dyo == -d);
            bool inx = (dx  == 0 || dx  == d || dx  == -d);
            if (iny && inx) {
                int ky = dyo / d + 1, kx = dx / d + 1;
                v += swsh[d] * wd[(c * CIN + ci) * 9 + ky * 3 + kx];
            }
        }
        g_W25[idx] = v;
    }
}

// ============================================================
// Kernel C: fused 25-tap conv (32->16) + pointwise (16->32) per batch.
// Tile: 128x8 pixels, 256 threads, 4 px/thread, halo 3.
// ============================================================
#define TX 128
#define TY 8
#define XS_STRIDE 136   // TX + 6 halo + 2 pad (keeps float4 reads in-bounds)
#define XS_ROWS   14    // TY + 6
#define SMEM_W25  (CIN * NTAPS * CMID)             // 12800
#define SMEM_M    (COUT * CMID)                    // 512
#define SMEM_FLOATS (SMEM_W25 + SMEM_M + COUT + XS_ROWS * XS_STRIDE)  // 15248

__global__ void __launch_bounds__(256, 2)
main_kernel(const float* __restrict__ x, float* __restrict__ y) {
    extern __shared__ float smem[];
    float* Wsh    = smem;                       // [ci][tap][c] 12800
    float* Msh    = smem + SMEM_W25;            // 512
    float* betash = Msh + SMEM_M;               // 32
    float* xs     = betash + COUT;              // 14 x 136

    const int b  = blockIdx.z;
    const int h0 = blockIdx.y * TY;
    const int w0 = blockIdx.x * TX;
    const int tid = threadIdx.x;
    const int ty  = tid >> 5;      // 0..7
    const int tx4 = tid & 31;      // 0..31; pixels w0 + tx4*4 + {0..3}

    for (int i = tid; i < SMEM_W25; i += 256) Wsh[i] = g_W25[i];
    for (int i = tid; i < SMEM_M;   i += 256) Msh[i] = g_M[b * SMEM_M + i];
    if (tid < COUT) betash[tid] = g_beta[b * COUT + tid];

    float acc[CMID][4];
#pragma unroll
    for (int c = 0; c < CMID; ++c)
#pragma unroll
        for (int p = 0; p < 4; ++p) acc[c][p] = 0.f;

#pragma unroll 1
    for (int ci = 0; ci < CIN; ++ci) {
        __syncthreads();
        // fill x tile (halo 3, zero pad outside image)
        const float* xp = x + (size_t)(b * CIN + ci) * PLANE;
        for (int i = tid; i < XS_ROWS * XS_STRIDE; i += 256) {
            int r  = i / XS_STRIDE;
            int cc = i - r * XS_STRIDE;
            int h = h0 - 3 + r;
            int w = w0 - 3 + cc;
            float v = 0.f;
            if ((unsigned)h < HH && (unsigned)w < WW) v = xp[h * WW + w];
            xs[i] = v;
        }
        __syncthreads();

        const float* wci = Wsh + ci * (NTAPS * CMID);
        const float* xbase = xs + ty * XS_STRIDE + tx4 * 4;

#pragma unroll
        for (int dyi = 0; dyi < 7; ++dyi) {
            const float4 a0 = *(const float4*)(xbase + dyi * XS_STRIDE);
            const float4 a1 = *(const float4*)(xbase + dyi * XS_STRIDE + 4);
            const float4 a2 = *(const float4*)(xbase + dyi * XS_STRIDE + 8);
            const float xr[12] = {a0.x, a0.y, a0.z, a0.w, a1.x, a1.y, a1.z, a1.w,
                                  a2.x, a2.y, a2.z, a2.w};
            const int aD = (dyi < 3) ? (3 - dyi) : (dyi - 3);
            const int nt = (dyi == 3) ? 7 : 3;
            const int tb = (dyi < 3) ? 3 * dyi : ((dyi == 3) ? 9 : 16 + 3 * (dyi - 4));
#pragma unroll
            for (int k = 0; k < nt; ++k) {
                const int dx = (dyi == 3) ? (k - 3) : ((k - 1) * aD);
                const float* wtap = wci + (tb + k) * CMID;
#pragma unroll
                for (int cq = 0; cq < 4; ++cq) {
                    const float4 wq = *(const float4*)(wtap + cq * 4);
                    const float wv[4] = {wq.x, wq.y, wq.z, wq.w};
#pragma unroll
                    for (int j = 0; j < 4; ++j) {
                        const int c = cq * 4 + j;
#pragma unroll
                        for (int p = 0; p < 4; ++p)
                            acc[c][p] += wv[j] * xr[3 + dx + p];
                    }
                }
            }
        }
    }

    // ---- epilogue: y[co] = sum_c M[co][c]*acc[c] + beta[co] ----
    const int h = h0 + ty;
    float* yp = y + ((size_t)(b * COUT) * HH + h) * WW + w0 + tx4 * 4;
#pragma unroll 1
    for (int co = 0; co < COUT; ++co) {
        const float* mrow = Msh + co * CMID;
        float4 o;
        float bt = betash[co];
        o.x = bt; o.y = bt; o.z = bt; o.w = bt;
#pragma unroll
        for (int cq = 0; cq < 4; ++cq) {
            const float4 mq = *(const float4*)(mrow + cq * 4);
            const float mv[4] = {mq.x, mq.y, mq.z, mq.w};
#pragma unroll
            for (int j = 0; j < 4; ++j) {
                const int c = cq * 4 + j;
                o.x += mv[j] * acc[c][0];
                o.y += mv[j] * acc[c][1];
                o.z += mv[j] * acc[c][2];
                o.w += mv[j] * acc[c][3];
            }
        }
        *(float4*)(yp + (size_t)co * PLANE) = o;
    }
}

// ============================================================
extern "C" void kernel_launch(void* const* d_in, const int* in_sizes, int n_in,
                              void* d_out, int out_size) {
    const float* x        = (const float*)d_in[0];
    const float* w1       = (const float*)d_in[1];
    const float* b1       = (const float*)d_in[2];
    const float* w2       = (const float*)d_in[3];
    const float* b2       = (const float*)d_in[4];
    const float* w3       = (const float*)d_in[5];
    const float* b3       = (const float*)d_in[6];
    const float* w4       = (const float*)d_in[7];
    const float* b4       = (const float*)d_in[8];
    const float* w5       = (const float*)d_in[9];
    const float* b5       = (const float*)d_in[10];
    const float* gcn_w    = (const float*)d_in[11];
    const float* gcn_b    = (const float*)d_in[12];
    const float* attn     = (const float*)d_in[13];
    const float* fusion_w = (const float*)d_in[14];
    const float* fusion_b = (const float*)d_in[15];
    float* y = (float*)d_out;

    static_assert(SMEM_FLOATS * 4 < 228 * 1024, "smem");
    cudaFuncSetAttribute(main_kernel, cudaFuncAttributeMaxDynamicSharedMemorySize,
                         SMEM_FLOATS * 4);

    stats_kernel<<<NPLANES, 256>>>(x);
    prep_kernel<<<1, 256>>>(x, w1, b1, w2, b2, w3, b3, w4, b4, w5, b5,
                            gcn_w, gcn_b, attn, fusion_w, fusion_b);
    dim3 grid(WW / TX, HH / TY, BATCH);
    main_kernel<<<grid, 256, SMEM_FLOATS * 4>>>(x, y);
}

// round 2
// speedup vs baseline: 1.5428x; 1.5428x over previous
#include <cuda_runtime.h>
#include <cuda_bf16.h>
#include <math.h>

// Problem constants
#define BATCH 8
#define CIN   32
#define CMID  16
#define COUT  32
#define HH    384
#define WW    384
#define PLANE (HH*WW)            // 147456
#define NPLANES (BATCH*CIN)      // 256
#define NTAPS 25
#define NSLICE 8                 // row-slices per plane for stats
#define SLICE_ROWS 48
#define SLICE_F4 (SLICE_ROWS*WW/4)   // 4608 float4 per slice

typedef unsigned long long ull;

// packed f32x2 helpers
#define FFMA2(acc, a, b) asm("fma.rn.f32x2 %0, %1, %2, %0;" : "+l"(acc) : "l"(a), "l"(b))
#define PACKF2(out, lo, hi) asm("mov.b64 %0, {%1, %2};" : "=l"(out) : "f"(lo), "f"(hi))
#define UNPACKF2(lo, hi, in) asm("mov.b64 {%0, %1}, %2;" : "=f"(lo), "=f"(hi) : "l"(in))

// ---- scratch (device globals; no allocation allowed) ----
__device__ float g_part[NPLANES * NSLICE * 13];  // per (plane,slice) partial stats
__device__ float g_W25[CIN * NTAPS * CMID];      // folded stage-1 conv weights [ci][tap][c]
__device__ float g_M[BATCH * COUT * CMID];       // per-batch pointwise weights
__device__ float g_beta[BATCH * COUT];           // per-batch bias

// ============================================================
// Kernel A: per-slice stats. grid = 2048 blocks (plane*8+slice), 256 threads.
// st layout: [0]=T, [1..3]=rowsum 0..2, [4..6]=rowsum 381..383,
//            [7..9]=colsum 0..2, [10..12]=colsum 381..383
// ============================================================
__device__ __forceinline__ float warp_red(float v) {
#pragma unroll
    for (int o = 16; o > 0; o >>= 1) v += __shfl_xor_sync(0xffffffffu, v, o);
    return v;
}

__global__ void stats_kernel(const float* __restrict__ x) {
    int blk = blockIdx.x;
    int plane = blk >> 3, slice = blk & 7;
    const float4* xp = (const float4*)(x + (size_t)plane * PLANE + (size_t)slice * SLICE_ROWS * WW);
    int tid = threadIdx.x;
    const bool bnd = (slice == 0 || slice == 7);

    float T = 0.f, c0 = 0.f, c1 = 0.f, c2 = 0.f, c3 = 0.f, c4 = 0.f, c5 = 0.f;
    float r0 = 0.f, r1 = 0.f, r2 = 0.f;

#pragma unroll
    for (int it = 0; it < SLICE_F4 / 256; ++it) {
        int i = tid + it * 256;
        float4 v = xp[i];
        float s4 = v.x + v.y + v.z + v.w;
        T += s4;
        int cq = i % 96;
        if (cq == 0)  { c0 += v.x; c1 += v.y; c2 += v.z; }
        if (cq == 95) { c3 += v.y; c4 += v.z; c5 += v.w; }
        if (bnd) {
            int lr = i / 96;                 // local row 0..47
            int key = (slice == 0) ? lr : (47 - lr);   // 0,1,2 are boundary rows
            if (key == 0) r0 += s4;          // row 0 / row 383
            else if (key == 1) r1 += s4;     // row 1 / row 382
            else if (key == 2) r2 += s4;     // row 2 / row 381
        }
    }

    __shared__ float s13[13];
    if (tid < 13) s13[tid] = 0.f;
    __syncthreads();

    T = warp_red(T);
    c0 = warp_red(c0); c1 = warp_red(c1); c2 = warp_red(c2);
    c3 = warp_red(c3); c4 = warp_red(c4); c5 = warp_red(c5);
    if (bnd) { r0 = warp_red(r0); r1 = warp_red(r1); r2 = warp_red(r2); }

    if ((tid & 31) == 0) {
        atomicAdd(&s13[0], T);
        atomicAdd(&s13[7], c0);  atomicAdd(&s13[8], c1);  atomicAdd(&s13[9], c2);
        atomicAdd(&s13[10], c3); atomicAdd(&s13[11], c4); atomicAdd(&s13[12], c5);
        if (bnd) {
            if (slice == 0) {            // rows 0,1,2 -> st[1],st[2],st[3]
                atomicAdd(&s13[1], r0); atomicAdd(&s13[2], r1); atomicAdd(&s13[3], r2);
            } else {                     // key0=row383->st[6], key1=row382->st[5], key2=row381->st[4]
                atomicAdd(&s13[6], r0); atomicAdd(&s13[5], r1); atomicAdd(&s13[4], r2);
            }
        }
    }
    __syncthreads();
    if (tid < 13) g_part[blk * 13 + tid] = s13[tid];
}

// partial sum of x over the valid shifted region for offset (dy,dx), exact borders
__device__ __forceinline__ float ps_fun(const float* __restrict__ xp,
                                        const float* __restrict__ st,
                                        int dy, int dx) {
    float s = st[0];
    if (dy > 0)      { for (int r = 0; r <  dy; ++r) s -= st[1 + r]; }
    else if (dy < 0) { for (int r = 0; r < -dy; ++r) s -= st[6 - r]; }
    if (dx > 0)      { for (int c = 0; c <  dx; ++c) s -= st[7 + c]; }
    else if (dx < 0) { for (int c = 0; c < -dx; ++c) s -= st[12 - c]; }
    if (dy != 0 && dx != 0) {
        int r0 = (dy > 0) ? 0 : HH + dy;
        int r1 = (dy > 0) ? dy - 1 : HH - 1;
        int c0 = (dx > 0) ? 0 : WW + dx;
        int c1 = (dx > 0) ? dx - 1 : WW - 1;
        for (int r = r0; r <= r1; ++r)
            for (int c = c0; c <= c1; ++c)
                s += xp[r * WW + c];  // add back doubly-subtracted corner
    }
    return s;
}

// ============================================================
// Kernel B: fold everything into W25 / M / beta. 1 block, 256 threads.
// ============================================================
__global__ void prep_kernel(const float* __restrict__ x,
                            const float* __restrict__ w1, const float* __restrict__ b1,
                            const float* __restrict__ w2, const float* __restrict__ b2,
                            const float* __restrict__ w3, const float* __restrict__ b3,
                            const float* __restrict__ w4, const float* __restrict__ b4,
                            const float* __restrict__ w5, const float* __restrict__ b5,
                            const float* __restrict__ gcn_w, const float* __restrict__ gcn_b,
                            const float* __restrict__ attn,
                            const float* __restrict__ fusion_w, const float* __restrict__ fusion_b) {
    __shared__ float nf[BATCH][5][CMID];   // branch node-feats WITHOUT biases
    __shared__ float zsh[BATCH][CMID];
    __shared__ float fnsh[BATCH][CMID];
    __shared__ float swsh[5];
    int tid = threadIdx.x;

    for (int i = tid; i < BATCH * 5 * CMID; i += 256) ((float*)nf)[i] = 0.f;
    if (tid == 0) {
        float m = attn[0];
        for (int i = 1; i < 5; ++i) m = fmaxf(m, attn[i]);
        float e[5], s = 0.f;
        for (int i = 0; i < 5; ++i) { e[i] = expf(attn[i] - m); s += e[i]; }
        for (int i = 0; i < 5; ++i) swsh[i] = e[i] / s;
    }
    __syncthreads();

    // ---- phase 1: exact per-branch node features (means with zero-padding) ----
    {
        int b = tid >> 5, ci = tid & 31;
        int plane = b * CIN + ci;
        const float* xp = x + (size_t)plane * PLANE;
        float st[13];
        for (int i = 0; i < 13; ++i) {
            float s = 0.f;
            for (int sl = 0; sl < NSLICE; ++sl) s += g_part[(plane * NSLICE + sl) * 13 + i];
            st[i] = s;
        }
        const float invHW = 1.0f / (float)PLANE;
        float xm = st[0] * invHW;
        for (int c = 0; c < CMID; ++c) {
            atomicAdd(&nf[b][0][c], w1[c * CIN + ci] * xm);   // f1: 1x1
            atomicAdd(&nf[b][4][c], w5[c * CIN + ci] * xm);   // f5: 1x1 on GAP
        }
        for (int d = 1; d <= 3; ++d) {
            float ps[9];
            for (int ky = 0; ky < 3; ++ky)
                for (int kx = 0; kx < 3; ++kx)
                    ps[ky * 3 + kx] = ps_fun(xp, st, d * (ky - 1), d * (kx - 1)) * invHW;
            const float* wd = (d == 1) ? w2 : (d == 2) ? w3 : w4;
            for (int c = 0; c < CMID; ++c) {
                float p = 0.f;
                for (int j = 0; j < 9; ++j) p += wd[(c * CIN + ci) * 9 + j] * ps[j];
                atomicAdd(&nf[b][d][c], p);
            }
        }
    }
    __syncthreads();

    // ---- phase 2: z = mean over branches (A_hat uniform) incl. biases ----
    if (tid < BATCH * CMID) {
        int b = tid >> 4, c = tid & 15;
        float s = nf[b][0][c] + nf[b][1][c] + nf[b][2][c] + nf[b][3][c] + nf[b][4][c]
                + b1[c] + b2[c] + b3[c] + b4[c] + b5[c];
        zsh[b][c] = 0.2f * s;
    }
    __syncthreads();

    // ---- phase 3: fn = z @ gcn_w + gcn_b ----
    if (tid < BATCH * CMID) {
        int b = tid >> 4, c = tid & 15;
        float s = gcn_b[c];
        for (int k = 0; k < CMID; ++k) s += zsh[b][k] * gcn_w[k * CMID + c];
        fnsh[b][c] = s;
    }
    __syncthreads();

    // ---- phase 4: M, beta ----
    {
        int b = tid >> 5, co = tid & 31;
        float bt = fusion_b[co];
        for (int c = 0; c < CMID; ++c) {
            float K = swsh[0] * b1[c] + swsh[1] * b2[c] + swsh[2] * b3[c] + swsh[3] * b4[c]
                    + swsh[4] * (nf[b][4][c] + b5[c]);       // f5 value (constant map)
            float m = fusion_w[co * CMID + c] * fnsh[b][c];
            g_M[(b * COUT + co) * CMID + c] = m;
            bt += m * K;
        }
        g_beta[b * COUT + co] = bt;
    }

    // ---- phase 5: folded 25-tap stage-1 weights, scaled by softmax weights ----
    for (int idx = tid; idx < CIN * NTAPS * CMID; idx += 256) {
        int ci = idx / (NTAPS * CMID);
        int r = idx - ci * (NTAPS * CMID);
        int t = r >> 4;
        int c = r & 15;
        int dyo, dx;
        if (t < 9)       { int g = t / 3; dyo = g - 3; dx = (t - g * 3 - 1) * (3 - g); }
        else if (t < 16) { dyo = 0; dx = t - 12; }
        else             { int g = (t - 16) / 3; dyo = g + 1; dx = ((t - 16) - g * 3 - 1) * (g + 1); }
        float v = 0.f;
        if (dyo == 0 && dx == 0) v += swsh[0] * w1[c * CIN + ci];
        for (int d = 1; d <= 3; ++d) {
            const float* wd = (d == 1) ? w2 : (d == 2) ? w3 : w4;
            bool iny = (dyo == 0 || dyo == d || dyo == -d);
            bool inx = (dx  == 0 || dx  == d || dx  == -d);
            if (iny && inx) {
                int ky = dyo / d + 1, kx = dx / d + 1;
                v += swsh[d] * wd[(c * CIN + ci) * 9 + ky * 3 + kx];
            }
        }
        g_W25[idx] = v;
    }
}

// ============================================================
// Kernel C: fused 25-tap conv (32->16) + pointwise (16->32) per batch.
// Tile: 128x8 pixels, 256 threads, 4 px/thread, halo 3.
// Inner math uses packed fma.rn.f32x2 over adjacent mid-channel pairs.
// ============================================================
#define TX 128
#define TY 8
#define XS_STRIDE 136   // TX + 6 halo + 2 pad (keeps float4 reads in-bounds)
#define XS_ROWS   14    // TY + 6
#define SMEM_W25  (CIN * NTAPS * CMID)             // 12800
#define SMEM_M    (COUT * CMID)                    // 512
#define SMEM_FLOATS (SMEM_W25 + SMEM_M + COUT + XS_ROWS * XS_STRIDE)  // 15248

__global__ void __launch_bounds__(256, 2)
main_kernel(const float* __restrict__ x, float* __restrict__ y) {
    extern __shared__ float smem[];
    float* Wsh    = smem;                       // [ci][tap][c] 12800
    float* Msh    = smem + SMEM_W25;            // 512
    float* betash = Msh + SMEM_M;               // 32
    float* xs     = betash + COUT;              // 14 x 136

    const int b  = blockIdx.z;
    const int h0 = blockIdx.y * TY;
    const int w0 = blockIdx.x * TX;
    const int tid = threadIdx.x;
    const int ty  = tid >> 5;      // 0..7
    const int tx4 = tid & 31;      // 0..31; pixels w0 + tx4*4 + {0..3}

    for (int i = tid; i < SMEM_W25; i += 256) Wsh[i] = g_W25[i];
    for (int i = tid; i < SMEM_M;   i += 256) Msh[i] = g_M[b * SMEM_M + i];
    if (tid < COUT) betash[tid] = g_beta[b * COUT + tid];

    // acc pairs over adjacent mid-channels: accp[cp][p] holds (c=2cp, c=2cp+1) for pixel p
    ull accp[CMID / 2][4];
#pragma unroll
    for (int cp = 0; cp < CMID / 2; ++cp)
#pragma unroll
        for (int p = 0; p < 4; ++p) accp[cp][p] = 0ull;

#pragma unroll 1
    for (int ci = 0; ci < CIN; ++ci) {
        __syncthreads();
        // fill x tile (halo 3, zero pad outside image)
        const float* xp = x + (size_t)(b * CIN + ci) * PLANE;
        for (int i = tid; i < XS_ROWS * XS_STRIDE; i += 256) {
            int r  = i / XS_STRIDE;
            int cc = i - r * XS_STRIDE;
            int h = h0 - 3 + r;
            int w = w0 - 3 + cc;
            float v = 0.f;
            if ((unsigned)h < HH && (unsigned)w < WW) v = xp[h * WW + w];
            xs[i] = v;
        }
        __syncthreads();

        const float* wci = Wsh + ci * (NTAPS * CMID);
        const float* xbase = xs + ty * XS_STRIDE + tx4 * 4;

#pragma unroll
        for (int dyi = 0; dyi < 7; ++dyi) {
            const float4 a0 = *(const float4*)(xbase + dyi * XS_STRIDE);
            const float4 a1 = *(const float4*)(xbase + dyi * XS_STRIDE + 4);
            const float4 a2 = *(const float4*)(xbase + dyi * XS_STRIDE + 8);
            const float xr[10] = {a0.x, a0.y, a0.z, a0.w, a1.x, a1.y, a1.z, a1.w,
                                  a2.x, a2.y};
            ull xb[10];  // broadcast pairs {x,x}
#pragma unroll
            for (int k = 0; k < 10; ++k) PACKF2(xb[k], xr[k], xr[k]);

            const int aD = (dyi < 3) ? (3 - dyi) : (dyi - 3);
            const int nt = (dyi == 3) ? 7 : 3;
            const int tb = (dyi < 3) ? 3 * dyi : ((dyi == 3) ? 9 : 16 + 3 * (dyi - 4));
#pragma unroll
            for (int k = 0; k < nt; ++k) {
                const int dx = (dyi == 3) ? (k - 3) : ((k - 1) * aD);
                const ull* wt = (const ull*)(wci + (tb + k) * CMID);
#pragma unroll
                for (int cp = 0; cp < CMID / 2; ++cp) {
                    const ull w2v = wt[cp];   // LDS.64 of {w[2cp], w[2cp+1]} (warp broadcast)
                    FFMA2(accp[cp][0], w2v, xb[3 + dx]);
                    FFMA2(accp[cp][1], w2v, xb[4 + dx]);
                    FFMA2(accp[cp][2], w2v, xb[5 + dx]);
                    FFMA2(accp[cp][3], w2v, xb[6 + dx]);
                }
            }
        }
    }

    // ---- epilogue: y[co] = sum_c M[co][c]*acc[c] + beta[co], packed over c pairs ----
    const int h = h0 + ty;
    float* yp = y + ((size_t)(b * COUT) * HH + h) * WW + w0 + tx4 * 4;
#pragma unroll 1
    for (int co = 0; co < COUT; ++co) {
        const ull* m64 = (const ull*)(Msh + co * CMID);
        ull o[4] = {0ull, 0ull, 0ull, 0ull};
#pragma unroll
        for (int cp = 0; cp < CMID / 2; ++cp) {
            const ull mv = m64[cp];
            FFMA2(o[0], mv, accp[cp][0]);
            FFMA2(o[1], mv, accp[cp][1]);
            FFMA2(o[2], mv, accp[cp][2]);
            FFMA2(o[3], mv, accp[cp][3]);
        }
        const float bt = betash[co];
        float4 ov;
        {
            float lo, hi;
            UNPACKF2(lo, hi, o[0]); ov.x = lo + hi + bt;
            UNPACKF2(lo, hi, o[1]); ov.y = lo + hi + bt;
            UNPACKF2(lo, hi, o[2]); ov.z = lo + hi + bt;
            UNPACKF2(lo, hi, o[3]); ov.w = lo + hi + bt;
        }
        *(float4*)(yp + (size_t)co * PLANE) = ov;
    }
}

// ============================================================
extern "C" void kernel_launch(void* const* d_in, const int* in_sizes, int n_in,
                              void* d_out, int out_size) {
    const float* x        = (const float*)d_in[0];
    const float* w1       = (const float*)d_in[1];
    const float* b1       = (const float*)d_in[2];
    const float* w2       = (const float*)d_in[3];
    const float* b2       = (const float*)d_in[4];
    const float* w3       = (const float*)d_in[5];
    const float* b3       = (const float*)d_in[6];
    const float* w4       = (const float*)d_in[7];
    const float* b4       = (const float*)d_in[8];
    const float* w5       = (const float*)d_in[9];
    const float* b5       = (const float*)d_in[10];
    const float* gcn_w    = (const float*)d_in[11];
    const float* gcn_b    = (const float*)d_in[12];
    const float* attn     = (const float*)d_in[13];
    const float* fusion_w = (const float*)d_in[14];
    const float* fusion_b = (const float*)d_in[15];
    float* y = (float*)d_out;

    static_assert(SMEM_FLOATS * 4 < 228 * 1024, "smem");
    cudaFuncSetAttribute(main_kernel, cudaFuncAttributeMaxDynamicSharedMemorySize,
                         SMEM_FLOATS * 4);

    stats_kernel<<<NPLANES * NSLICE, 256>>>(x);
    prep_kernel<<<1, 256>>>(x, w1, b1, w2, b2, w3, b3, w4, b4, w5, b5,
                            gcn_w, gcn_b, attn, fusion_w, fusion_b);
    dim3 grid(WW / TX, HH / TY, BATCH);
    main_kernel<<<grid, 256, SMEM_FLOATS * 4>>>(x, y);
}